// round 5
// baseline (speedup 1.0000x reference)
#include <cuda_runtime.h>
#include <cstdint>

// ---------------------------------------------------------------------------
// Attention_12970801234467 — 3xTF32, split-at-staging version
//   q = Q@W+b ; k = K@W+b ; v = V@W+b   (same W for all three, per reference)
//   logits = q k^T / 32 ; w = softmax(logits) ; out = w v
// Shapes: B=8, S=2048, D=1024.
// GEMMs: mma.sync m16n8k8 tf32, hi/lo split performed ONCE per tile element
// while staging into SMEM (4 planes: Ahi/Alo/Bhi/Blo). Mainloop is pure
// LDS -> HMMA. 2 CTAs/SM.
// ---------------------------------------------------------------------------

#define BATCH 8
#define SEQ   2048
#define DIM   1024
#define NROWS (BATCH * SEQ)        // 16384

#define BM 128
#define BN 128
#define BK 16
#define SMLD 136                   // padded plane stride (136 mod 32 = 8): conflict-free

__device__ float g_q[(size_t)NROWS * DIM];
__device__ float g_k[(size_t)NROWS * DIM];
__device__ float g_v[(size_t)NROWS * DIM];
__device__ float g_logits[(size_t)BATCH * SEQ * SEQ];

// ---- tf32 split: x = hi + lo, both tf32-representable (bit patterns) ------
__device__ __forceinline__ void split_tf32(float x, uint32_t& hi, uint32_t& lo) {
    uint32_t h;
    asm("cvt.rna.tf32.f32 %0, %1;" : "=r"(h) : "f"(x));
    float r = x - __uint_as_float(h);
    uint32_t l;
    asm("cvt.rna.tf32.f32 %0, %1;" : "=r"(l) : "f"(r));
    hi = h; lo = l;
}

__device__ __forceinline__ void mma1688(float c[4],
                                        uint32_t a0, uint32_t a1, uint32_t a2, uint32_t a3,
                                        uint32_t b0, uint32_t b1) {
    asm volatile(
        "mma.sync.aligned.m16n8k8.row.col.f32.tf32.tf32.f32 "
        "{%0,%1,%2,%3}, {%4,%5,%6,%7}, {%8,%9}, {%0,%1,%2,%3};\n"
        : "+f"(c[0]), "+f"(c[1]), "+f"(c[2]), "+f"(c[3])
        : "r"(a0), "r"(a1), "r"(a2), "r"(a3), "r"(b0), "r"(b1));
}

// ---------------------------------------------------------------------------
// C = alpha * A * op(B) (+ bias).  A:[M,K] rm.  TRANSB? B:[N,K] rm : B:[K,N] rm.
// Batched over blockIdx.z. 256 threads = 8 warps (2 m x 4 n), warp tile 64x32.
// ---------------------------------------------------------------------------
template <bool TRANSB, bool BIAS>
__global__ __launch_bounds__(256, 2)
void gemm_tf32(const float* __restrict__ A, const float* __restrict__ Bm,
               const float* __restrict__ bias, float* __restrict__ C,
               int M, int N, int K,
               long long sA, long long sB, long long sC, float alpha)
{
    __shared__ uint32_t Ash[BK][SMLD];
    __shared__ uint32_t Asl[BK][SMLD];
    __shared__ uint32_t Bsh[BK][SMLD];
    __shared__ uint32_t Bsl[BK][SMLD];

    const int tid  = threadIdx.x;
    const int warp = tid >> 5;
    const int lane = tid & 31;
    const int gid  = lane >> 2;    // 0..7
    const int tig  = lane & 3;     // 0..3
    const int wm   = warp & 1;     // 0..1 (m)
    const int wn   = warp >> 1;    // 0..3 (n)

    const long long z = blockIdx.z;
    A  += z * sA;
    Bm += z * sB;
    C  += z * sC;

    const int mbase = blockIdx.y * BM;
    const int nbase = blockIdx.x * BN;

    float acc[4][4][4];
#pragma unroll
    for (int i = 0; i < 4; i++)
#pragma unroll
        for (int j = 0; j < 4; j++)
#pragma unroll
            for (int r = 0; r < 4; r++) acc[i][j][r] = 0.0f;

    float4 pa[2], pb[2];

    // Global loaders: each thread stages 2 float4 of A and of B per tile.
    auto ldg_tiles = [&](int kt) {
#pragma unroll
        for (int i = 0; i < 2; i++) {
            const int idx = tid + i * 256;              // 0..511
            {   // A: 128 rows x 16 k, float4 along k
                const int r  = idx & 127;
                const int kq = idx >> 7;                // 0..3
                pa[i] = *(const float4*)(A + (long long)(mbase + r) * K + kt + kq * 4);
            }
            if (TRANSB) {                                // B [N,K]: float4 along k
                const int r  = idx & 127;
                const int kq = idx >> 7;
                pb[i] = *(const float4*)(Bm + (long long)(nbase + r) * K + kt + kq * 4);
            } else {                                     // B [K,N]: float4 along n
                const int kk = idx >> 5;                // 0..15
                const int n4 = idx & 31;
                pb[i] = *(const float4*)(Bm + (long long)(kt + kk) * N + nbase + n4 * 4);
            }
        }
    };

    // Stage into SMEM with hi/lo split (once per element).
    auto sts_tiles = [&]() {
#pragma unroll
        for (int i = 0; i < 2; i++) {
            const int idx = tid + i * 256;
            {   // A scatter: plane[k][m]
                const int r  = idx & 127;
                const int kq = idx >> 7;
                const float av[4] = {pa[i].x, pa[i].y, pa[i].z, pa[i].w};
#pragma unroll
                for (int c = 0; c < 4; c++) {
                    uint32_t h, l;
                    split_tf32(av[c], h, l);
                    Ash[kq * 4 + c][r] = h;
                    Asl[kq * 4 + c][r] = l;
                }
            }
            const float bv[4] = {pb[i].x, pb[i].y, pb[i].z, pb[i].w};
            if (TRANSB) {
                const int r  = idx & 127;
                const int kq = idx >> 7;
#pragma unroll
                for (int c = 0; c < 4; c++) {
                    uint32_t h, l;
                    split_tf32(bv[c], h, l);
                    Bsh[kq * 4 + c][r] = h;
                    Bsl[kq * 4 + c][r] = l;
                }
            } else {
                const int kk = idx >> 5;
                const int n4 = idx & 31;
#pragma unroll
                for (int c = 0; c < 4; c++) {
                    uint32_t h, l;
                    split_tf32(bv[c], h, l);
                    Bsh[kk][n4 * 4 + c] = h;
                    Bsl[kk][n4 * 4 + c] = l;
                }
            }
        }
    };

    const int T = K / BK;
    ldg_tiles(0);

    for (int t = 0; t < T; t++) {
        __syncthreads();               // previous compute finished reading smem
        sts_tiles();
        __syncthreads();               // tile visible
        if (t + 1 < T) ldg_tiles((t + 1) * BK);   // prefetch next (hidden by compute)

#pragma unroll
        for (int ks = 0; ks < 2; ks++) {
            const int kb = ks * 8;
            uint32_t bh[4][2], bl[4][2];
#pragma unroll
            for (int na = 0; na < 4; na++) {
                const int n0 = wn * 32 + na * 8 + gid;
                bh[na][0] = Bsh[kb + tig][n0];
                bh[na][1] = Bsh[kb + tig + 4][n0];
                bl[na][0] = Bsl[kb + tig][n0];
                bl[na][1] = Bsl[kb + tig + 4][n0];
            }
#pragma unroll
            for (int ma = 0; ma < 4; ma++) {
                const int m0 = wm * 64 + ma * 16 + gid;
                const uint32_t ah0 = Ash[kb + tig][m0];
                const uint32_t ah1 = Ash[kb + tig][m0 + 8];
                const uint32_t ah2 = Ash[kb + tig + 4][m0];
                const uint32_t ah3 = Ash[kb + tig + 4][m0 + 8];
                const uint32_t al0 = Asl[kb + tig][m0];
                const uint32_t al1 = Asl[kb + tig][m0 + 8];
                const uint32_t al2 = Asl[kb + tig + 4][m0];
                const uint32_t al3 = Asl[kb + tig + 4][m0 + 8];
#pragma unroll
                for (int na = 0; na < 4; na++) {
                    mma1688(acc[ma][na], ah0, ah1, ah2, ah3, bh[na][0], bh[na][1]);
                    mma1688(acc[ma][na], ah0, ah1, ah2, ah3, bl[na][0], bl[na][1]);
                    mma1688(acc[ma][na], al0, al1, al2, al3, bh[na][0], bh[na][1]);
                }
            }
        }
    }

    // Epilogue: c0,c1 -> (row, col..col+1), c2,c3 -> (row+8, ...)
#pragma unroll
    for (int ma = 0; ma < 4; ma++) {
        const int row0 = mbase + wm * 64 + ma * 16 + gid;
#pragma unroll
        for (int na = 0; na < 4; na++) {
            const int col = nbase + wn * 32 + na * 8 + tig * 2;
            float2 o0, o1;
            o0.x = alpha * acc[ma][na][0];
            o0.y = alpha * acc[ma][na][1];
            o1.x = alpha * acc[ma][na][2];
            o1.y = alpha * acc[ma][na][3];
            if (BIAS) {
                o0.x += bias[col];     o0.y += bias[col + 1];
                o1.x += bias[col];     o1.y += bias[col + 1];
            }
            *(float2*)(C + (long long)row0 * N + col)       = o0;
            *(float2*)(C + (long long)(row0 + 8) * N + col) = o1;
        }
    }
}

// ---------------------------------------------------------------------------
// Row softmax over S=2048, in place. One 256-thread block per row.
// ---------------------------------------------------------------------------
__global__ __launch_bounds__(256)
void softmax2048(float* __restrict__ logits)
{
    const long long row = blockIdx.x;
    float* p = logits + row * (long long)SEQ;
    const int tid = threadIdx.x;

    __shared__ float red[8];
    __shared__ float bcast;

    float v[8];
    float m = -1e30f;
#pragma unroll
    for (int i = 0; i < 8; i++) {
        v[i] = p[tid + i * 256];
        m = fmaxf(m, v[i]);
    }
#pragma unroll
    for (int o = 16; o > 0; o >>= 1) m = fmaxf(m, __shfl_xor_sync(0xffffffffu, m, o));
    if ((tid & 31) == 0) red[tid >> 5] = m;
    __syncthreads();
    if (tid == 0) {
        float t = red[0];
#pragma unroll
        for (int i = 1; i < 8; i++) t = fmaxf(t, red[i]);
        bcast = t;
    }
    __syncthreads();
    const float rmax = bcast;

    float s = 0.0f;
#pragma unroll
    for (int i = 0; i < 8; i++) {
        v[i] = expf(v[i] - rmax);
        s += v[i];
    }
#pragma unroll
    for (int o = 16; o > 0; o >>= 1) s += __shfl_xor_sync(0xffffffffu, s, o);
    if ((tid & 31) == 0) red[tid >> 5] = s;
    __syncthreads();
    if (tid == 0) {
        float t = 0.0f;
#pragma unroll
        for (int i = 0; i < 8; i++) t += red[i];
        bcast = 1.0f / t;
    }
    __syncthreads();
    const float inv = bcast;

#pragma unroll
    for (int i = 0; i < 8; i++) p[tid + i * 256] = v[i] * inv;
}

// ---------------------------------------------------------------------------
extern "C" void kernel_launch(void* const* d_in, const int* in_sizes, int n_in,
                              void* d_out, int out_size)
{
    const float* query = (const float*)d_in[0];
    const float* key   = (const float*)d_in[1];
    const float* value = (const float*)d_in[2];
    const float* Wq    = (const float*)d_in[3];
    const float* bq    = (const float*)d_in[4];
    float* out = (float*)d_out;

    float *q, *k, *v, *lg;
    cudaGetSymbolAddress((void**)&q,  g_q);
    cudaGetSymbolAddress((void**)&k,  g_k);
    cudaGetSymbolAddress((void**)&v,  g_v);
    cudaGetSymbolAddress((void**)&lg, g_logits);

    const dim3 blk(256);

    // Stage 1: projections  Y = X @ W + b   (M=16384, N=1024, K=1024)
    {
        dim3 g(DIM / BN, NROWS / BM, 1);
        gemm_tf32<false, true><<<g, blk>>>(query, Wq, bq, q, NROWS, DIM, DIM, 0, 0, 0, 1.0f);
        gemm_tf32<false, true><<<g, blk>>>(key,   Wq, bq, k, NROWS, DIM, DIM, 0, 0, 0, 1.0f);
        gemm_tf32<false, true><<<g, blk>>>(value, Wq, bq, v, NROWS, DIM, DIM, 0, 0, 0, 1.0f);
    }

    // Stage 2: logits[b] = q[b] @ k[b]^T / 32   (M=N=2048, K=1024, batched)
    {
        dim3 g(SEQ / BN, SEQ / BM, BATCH);
        gemm_tf32<true, false><<<g, blk>>>(q, k, nullptr, lg,
                                           SEQ, SEQ, DIM,
                                           (long long)SEQ * DIM, (long long)SEQ * DIM,
                                           (long long)SEQ * SEQ, 0.03125f);
    }

    // Stage 3: softmax rows (B*S rows of length S)
    softmax2048<<<NROWS, 256>>>(lg);

    // Stage 4: out[b] = w[b] @ v[b]   (M=2048, N=1024, K=2048, batched)
    {
        dim3 g(DIM / BN, SEQ / BM, BATCH);
        gemm_tf32<false, false><<<g, blk>>>(lg, v, nullptr, out,
                                            SEQ, DIM, SEQ,
                                            (long long)SEQ * SEQ, (long long)SEQ * DIM,
                                            (long long)SEQ * DIM, 1.0f);
    }
}

// round 6
// speedup vs baseline: 1.4690x; 1.4690x over previous
#include <cuda_runtime.h>
#include <cuda_bf16.h>
#include <cstdint>

// ---------------------------------------------------------------------------
// Attention_12970801234467 — bf16x3 tensor-core version (m16n8k16)
//   q = Q@W+b ; k = K@W+b ; v = V@W+b   (same W for all three, per reference)
//   logits = q k^T / 32 ; w = softmax(logits) ; out = w v
// Shapes: B=8, S=2048, D=1024.
// Each fp32 operand is split x = hi + lo (both bf16); product uses
// hi*hi + hi*lo + lo*hi (3 MMAs) with fp32 accumulation -> ~1e-5 rel accuracy.
// SMEM holds packed bf16 k-pairs (hi and lo planes). Mainloop: LDS -> HMMA.
// ---------------------------------------------------------------------------

#define BATCH 8
#define SEQ   2048
#define DIM   1024
#define NROWS (BATCH * SEQ)        // 16384

#define BM 128
#define BN 128
#define BK 16                      // k16 per tile = one m16n8k16 step
#define SMLD 136                   // padded plane stride (136 mod 32 = 8)

__device__ float g_q[(size_t)NROWS * DIM];
__device__ float g_k[(size_t)NROWS * DIM];
__device__ float g_v[(size_t)NROWS * DIM];
__device__ float g_logits[(size_t)BATCH * SEQ * SEQ];

// ---- bf16 split of two floats -> packed hi-pair / lo-pair ------------------
__device__ __forceinline__ void split2(float x, float y, uint32_t& hp, uint32_t& lp) {
    __nv_bfloat16 hx = __float2bfloat16_rn(x);
    __nv_bfloat16 hy = __float2bfloat16_rn(y);
    float rx = x - __bfloat162float(hx);      // exact residual
    float ry = y - __bfloat162float(hy);
    __nv_bfloat16 lx = __float2bfloat16_rn(rx);
    __nv_bfloat16 ly = __float2bfloat16_rn(ry);
    hp = (uint32_t)__bfloat16_as_ushort(hx) | ((uint32_t)__bfloat16_as_ushort(hy) << 16);
    lp = (uint32_t)__bfloat16_as_ushort(lx) | ((uint32_t)__bfloat16_as_ushort(ly) << 16);
}

__device__ __forceinline__ void mma16816(float c[4],
                                         uint32_t a0, uint32_t a1, uint32_t a2, uint32_t a3,
                                         uint32_t b0, uint32_t b1) {
    asm volatile(
        "mma.sync.aligned.m16n8k16.row.col.f32.bf16.bf16.f32 "
        "{%0,%1,%2,%3}, {%4,%5,%6,%7}, {%8,%9}, {%0,%1,%2,%3};\n"
        : "+f"(c[0]), "+f"(c[1]), "+f"(c[2]), "+f"(c[3])
        : "r"(a0), "r"(a1), "r"(a2), "r"(a3), "r"(b0), "r"(b1));
}

// ---------------------------------------------------------------------------
// C = alpha * A * op(B) (+ bias).  A:[M,K] rm.  TRANSB? B:[N,K] rm : B:[K,N] rm.
// Batched over blockIdx.z. 256 threads = 8 warps (2 m x 4 n), warp tile 64x32.
// SMEM planes: P[kpair][pos], kpair = k/2 (0..7), each word = bf16x2 (k, k+1).
// ---------------------------------------------------------------------------
template <bool TRANSB, bool BIAS>
__global__ __launch_bounds__(256, 2)
void gemm_bf16x3(const float* __restrict__ A, const float* __restrict__ Bm,
                 const float* __restrict__ bias, float* __restrict__ C,
                 int M, int N, int K,
                 long long sA, long long sB, long long sC, float alpha)
{
    __shared__ uint32_t Ash[8][SMLD];
    __shared__ uint32_t Asl[8][SMLD];
    __shared__ uint32_t Bsh[8][SMLD];
    __shared__ uint32_t Bsl[8][SMLD];

    const int tid  = threadIdx.x;
    const int warp = tid >> 5;
    const int lane = tid & 31;
    const int gid  = lane >> 2;    // 0..7
    const int tig  = lane & 3;     // 0..3
    const int wm   = warp & 1;     // 0..1 (m)
    const int wn   = warp >> 1;    // 0..3 (n)

    const long long z = blockIdx.z;
    A  += z * sA;
    Bm += z * sB;
    C  += z * sC;

    const int mbase = blockIdx.y * BM;
    const int nbase = blockIdx.x * BN;

    float acc[4][4][4];
#pragma unroll
    for (int i = 0; i < 4; i++)
#pragma unroll
        for (int j = 0; j < 4; j++)
#pragma unroll
            for (int r = 0; r < 4; r++) acc[i][j][r] = 0.0f;

    float4 pa[2], pb[2];

    // ---- global loaders -> registers ----
    auto ldg_tiles = [&](int kt) {
#pragma unroll
        for (int i = 0; i < 2; i++) {
            const int idx = tid + i * 256;              // 0..511
            // A: 128 rows x 16 k, float4 along k
            const int r  = idx & 127;
            const int kq = idx >> 7;                    // 0..3
            pa[i] = *(const float4*)(A + (long long)(mbase + r) * K + kt + kq * 4);
            if (TRANSB) {                                // B [N,K]: float4 along k
                pb[i] = *(const float4*)(Bm + (long long)(nbase + r) * K + kt + kq * 4);
            }
        }
        if (!TRANSB) {                                   // B [K,N]: k-pair rows
            const int p  = tid >> 5;                     // 0..7 (k-pair)
            const int n4 = tid & 31;                     // 0..31 (float4 along n)
            pb[0] = *(const float4*)(Bm + (long long)(kt + 2 * p)     * N + nbase + n4 * 4);
            pb[1] = *(const float4*)(Bm + (long long)(kt + 2 * p + 1) * N + nbase + n4 * 4);
        }
    };

    // ---- split + pack + store to SMEM planes ----
    auto sts_tiles = [&]() {
#pragma unroll
        for (int i = 0; i < 2; i++) {
            const int idx = tid + i * 256;
            const int r  = idx & 127;
            const int kq = idx >> 7;                    // float4 -> k-pairs 2kq, 2kq+1
            uint32_t h, l;
            split2(pa[i].x, pa[i].y, h, l);
            Ash[kq * 2 + 0][r] = h;  Asl[kq * 2 + 0][r] = l;
            split2(pa[i].z, pa[i].w, h, l);
            Ash[kq * 2 + 1][r] = h;  Asl[kq * 2 + 1][r] = l;
            if (TRANSB) {
                split2(pb[i].x, pb[i].y, h, l);
                Bsh[kq * 2 + 0][r] = h;  Bsl[kq * 2 + 0][r] = l;
                split2(pb[i].z, pb[i].w, h, l);
                Bsh[kq * 2 + 1][r] = h;  Bsl[kq * 2 + 1][r] = l;
            }
        }
        if (!TRANSB) {
            const int p  = tid >> 5;
            const int n4 = tid & 31;
            const float r0[4] = {pb[0].x, pb[0].y, pb[0].z, pb[0].w};  // k = 2p
            const float r1[4] = {pb[1].x, pb[1].y, pb[1].z, pb[1].w};  // k = 2p+1
#pragma unroll
            for (int c = 0; c < 4; c++) {
                uint32_t h, l;
                split2(r0[c], r1[c], h, l);              // pack along k
                Bsh[p][n4 * 4 + c] = h;
                Bsl[p][n4 * 4 + c] = l;
            }
        }
    };

    const int T = K / BK;
    ldg_tiles(0);

    for (int t = 0; t < T; t++) {
        __syncthreads();                     // readers of previous tile done
        sts_tiles();
        __syncthreads();                     // tile visible
        if (t + 1 < T) ldg_tiles((t + 1) * BK);   // prefetch overlapped w/ compute

        // ---- one m16n8k16 step over the k16 tile ----
        uint32_t bh[4][2], bl[4][2];
#pragma unroll
        for (int na = 0; na < 4; na++) {
            const int n0 = wn * 32 + na * 8 + gid;
            bh[na][0] = Bsh[tig][n0];
            bh[na][1] = Bsh[4 + tig][n0];
            bl[na][0] = Bsl[tig][n0];
            bl[na][1] = Bsl[4 + tig][n0];
        }
#pragma unroll
        for (int ma = 0; ma < 4; ma++) {
            const int m0 = wm * 64 + ma * 16 + gid;
            const uint32_t ah0 = Ash[tig][m0];
            const uint32_t ah1 = Ash[tig][m0 + 8];
            const uint32_t ah2 = Ash[4 + tig][m0];
            const uint32_t ah3 = Ash[4 + tig][m0 + 8];
            const uint32_t al0 = Asl[tig][m0];
            const uint32_t al1 = Asl[tig][m0 + 8];
            const uint32_t al2 = Asl[4 + tig][m0];
            const uint32_t al3 = Asl[4 + tig][m0 + 8];
#pragma unroll
            for (int na = 0; na < 4; na++) {
                mma16816(acc[ma][na], ah0, ah1, ah2, ah3, bh[na][0], bh[na][1]);
                mma16816(acc[ma][na], ah0, ah1, ah2, ah3, bl[na][0], bl[na][1]);
                mma16816(acc[ma][na], al0, al1, al2, al3, bh[na][0], bh[na][1]);
            }
        }
    }

    // ---- epilogue: c0,c1 -> (row, col..col+1), c2,c3 -> (row+8, ...) ----
#pragma unroll
    for (int ma = 0; ma < 4; ma++) {
        const int row0 = mbase + wm * 64 + ma * 16 + gid;
#pragma unroll
        for (int na = 0; na < 4; na++) {
            const int col = nbase + wn * 32 + na * 8 + tig * 2;
            float2 o0, o1;
            o0.x = alpha * acc[ma][na][0];
            o0.y = alpha * acc[ma][na][1];
            o1.x = alpha * acc[ma][na][2];
            o1.y = alpha * acc[ma][na][3];
            if (BIAS) {
                o0.x += bias[col];     o0.y += bias[col + 1];
                o1.x += bias[col];     o1.y += bias[col + 1];
            }
            *(float2*)(C + (long long)row0 * N + col)       = o0;
            *(float2*)(C + (long long)(row0 + 8) * N + col) = o1;
        }
    }
}

// ---------------------------------------------------------------------------
// Row softmax over S=2048, in place. One 256-thread block per row.
// ---------------------------------------------------------------------------
__global__ __launch_bounds__(256)
void softmax2048(float* __restrict__ logits)
{
    const long long row = blockIdx.x;
    float* p = logits + row * (long long)SEQ;
    const int tid = threadIdx.x;

    __shared__ float red[8];
    __shared__ float bcast;

    float v[8];
    float m = -1e30f;
#pragma unroll
    for (int i = 0; i < 8; i++) {
        v[i] = p[tid + i * 256];
        m = fmaxf(m, v[i]);
    }
#pragma unroll
    for (int o = 16; o > 0; o >>= 1) m = fmaxf(m, __shfl_xor_sync(0xffffffffu, m, o));
    if ((tid & 31) == 0) red[tid >> 5] = m;
    __syncthreads();
    if (tid == 0) {
        float t = red[0];
#pragma unroll
        for (int i = 1; i < 8; i++) t = fmaxf(t, red[i]);
        bcast = t;
    }
    __syncthreads();
    const float rmax = bcast;

    float s = 0.0f;
#pragma unroll
    for (int i = 0; i < 8; i++) {
        v[i] = expf(v[i] - rmax);
        s += v[i];
    }
#pragma unroll
    for (int o = 16; o > 0; o >>= 1) s += __shfl_xor_sync(0xffffffffu, s, o);
    if ((tid & 31) == 0) red[tid >> 5] = s;
    __syncthreads();
    if (tid == 0) {
        float t = 0.0f;
#pragma unroll
        for (int i = 0; i < 8; i++) t += red[i];
        bcast = 1.0f / t;
    }
    __syncthreads();
    const float inv = bcast;

#pragma unroll
    for (int i = 0; i < 8; i++) p[tid + i * 256] = v[i] * inv;
}

// ---------------------------------------------------------------------------
extern "C" void kernel_launch(void* const* d_in, const int* in_sizes, int n_in,
                              void* d_out, int out_size)
{
    const float* query = (const float*)d_in[0];
    const float* key   = (const float*)d_in[1];
    const float* value = (const float*)d_in[2];
    const float* Wq    = (const float*)d_in[3];
    const float* bq    = (const float*)d_in[4];
    float* out = (float*)d_out;

    float *q, *k, *v, *lg;
    cudaGetSymbolAddress((void**)&q,  g_q);
    cudaGetSymbolAddress((void**)&k,  g_k);
    cudaGetSymbolAddress((void**)&v,  g_v);
    cudaGetSymbolAddress((void**)&lg, g_logits);

    const dim3 blk(256);

    // Stage 1: projections  Y = X @ W + b   (M=16384, N=1024, K=1024)
    {
        dim3 g(DIM / BN, NROWS / BM, 1);
        gemm_bf16x3<false, true><<<g, blk>>>(query, Wq, bq, q, NROWS, DIM, DIM, 0, 0, 0, 1.0f);
        gemm_bf16x3<false, true><<<g, blk>>>(key,   Wq, bq, k, NROWS, DIM, DIM, 0, 0, 0, 1.0f);
        gemm_bf16x3<false, true><<<g, blk>>>(value, Wq, bq, v, NROWS, DIM, DIM, 0, 0, 0, 1.0f);
    }

    // Stage 2: logits[b] = q[b] @ k[b]^T / 32   (M=N=2048, K=1024, batched)
    {
        dim3 g(SEQ / BN, SEQ / BM, BATCH);
        gemm_bf16x3<true, false><<<g, blk>>>(q, k, nullptr, lg,
                                             SEQ, SEQ, DIM,
                                             (long long)SEQ * DIM, (long long)SEQ * DIM,
                                             (long long)SEQ * SEQ, 0.03125f);
    }

    // Stage 3: softmax rows (B*S rows of length S)
    softmax2048<<<NROWS, 256>>>(lg);

    // Stage 4: out[b] = w[b] @ v[b]   (M=2048, N=1024, K=2048, batched)
    {
        dim3 g(DIM / BN, SEQ / BM, BATCH);
        gemm_bf16x3<false, false><<<g, blk>>>(lg, v, nullptr, out,
                                              SEQ, DIM, SEQ,
                                              (long long)SEQ * SEQ, (long long)SEQ * DIM,
                                              (long long)SEQ * DIM, 1.0f);
    }
}

// round 8
// speedup vs baseline: 1.8592x; 1.2656x over previous
#include <cuda_runtime.h>
#include <cuda_bf16.h>
#include <cstdint>

// ---------------------------------------------------------------------------
// Attention_12970801234467 — bf16x3 mma.sync, pre-split planes + ldmatrix
//   q = Q@W+b ; k = K@W+b ; v = V@W+b ; logits = q k^T/32 ; softmax ; out = w v
// B=8, S=2048, D=1024.
// All GEMMs NT on bf16 hi/lo planes (A:[M,K], B:[N,K], K-contiguous):
//   C = (Ah+Al)(Bh+Bl)^T ~= Ah Bh + Ah Bl + Al Bh   (fp32 accum)
// CTA tile 128x256, 8 warps (2m x 4n), warp tile 64x64, BK=32,
// cp.async 3-stage pipeline (1 barrier per BK), ldmatrix.x4 fragments.
// ---------------------------------------------------------------------------

#define BATCH 8
#define SEQ   2048
#define DIM   1024
#define NROWS (BATCH * SEQ)          // 16384

typedef __nv_bfloat16 bf16;

// ---- global scratch --------------------------------------------------------
__device__ uint4 g_ih [(size_t)NROWS * DIM / 8];      // input hi (reused Q,K,V)
__device__ uint4 g_il [(size_t)NROWS * DIM / 8];
__device__ uint4 g_wth[(size_t)DIM * DIM / 8];        // W^T hi  [N,K]
__device__ uint4 g_wtl[(size_t)DIM * DIM / 8];
__device__ uint4 g_qh [(size_t)NROWS * DIM / 8];
__device__ uint4 g_ql [(size_t)NROWS * DIM / 8];
__device__ uint4 g_kh [(size_t)NROWS * DIM / 8];
__device__ uint4 g_kl [(size_t)NROWS * DIM / 8];
__device__ float g_v  [(size_t)NROWS * DIM];          // v fp32 (pre-transpose)
__device__ uint4 g_vth[(size_t)NROWS * DIM / 8];      // v^T hi  [B][D][S]
__device__ uint4 g_vtl[(size_t)NROWS * DIM / 8];
__device__ float g_logits[(size_t)BATCH * SEQ * SEQ];
__device__ uint4 g_wh [(size_t)BATCH * SEQ * SEQ / 8];
__device__ uint4 g_wl [(size_t)BATCH * SEQ * SEQ / 8];

// ---- helpers ---------------------------------------------------------------
__device__ __forceinline__ uint32_t smem_u32(const void* p) {
    uint32_t a;
    asm("{ .reg .u64 t; cvta.to.shared.u64 t, %1; cvt.u32.u64 %0, t; }"
        : "=r"(a) : "l"(p));
    return a;
}
__device__ __forceinline__ void cp16(uint32_t dst, const void* src) {
    asm volatile("cp.async.cg.shared.global [%0], [%1], 16;" :: "r"(dst), "l"(src));
}
#define CP_COMMIT() asm volatile("cp.async.commit_group;" ::: "memory")
#define CP_WAIT1()  asm volatile("cp.async.wait_group 1;" ::: "memory")
#define CP_WAIT0()  asm volatile("cp.async.wait_group 0;" ::: "memory")

__device__ __forceinline__ void ldsm4(uint32_t& r0, uint32_t& r1, uint32_t& r2,
                                      uint32_t& r3, uint32_t addr) {
    asm volatile("ldmatrix.sync.aligned.m8n8.x4.shared.b16 {%0,%1,%2,%3}, [%4];"
                 : "=r"(r0), "=r"(r1), "=r"(r2), "=r"(r3) : "r"(addr));
}
__device__ __forceinline__ void mma16816(float c[4],
                                         uint32_t a0, uint32_t a1, uint32_t a2, uint32_t a3,
                                         uint32_t b0, uint32_t b1) {
    asm volatile(
        "mma.sync.aligned.m16n8k16.row.col.f32.bf16.bf16.f32 "
        "{%0,%1,%2,%3}, {%4,%5,%6,%7}, {%8,%9}, {%0,%1,%2,%3};\n"
        : "+f"(c[0]), "+f"(c[1]), "+f"(c[2]), "+f"(c[3])
        : "r"(a0), "r"(a1), "r"(a2), "r"(a3), "r"(b0), "r"(b1));
}
__device__ __forceinline__ void split1(float x, bf16& h, bf16& l) {
    h = __float2bfloat16_rn(x);
    l = __float2bfloat16_rn(x - __bfloat162float(h));
}

// ---------------------------------------------------------------------------
// Elementwise split: fp32[n] -> hi/lo bf16[n].
// ---------------------------------------------------------------------------
__global__ __launch_bounds__(256)
void split_pass(const float* __restrict__ in, bf16* __restrict__ oh,
                bf16* __restrict__ ol)
{
    const long long i = ((long long)blockIdx.x * 256 + threadIdx.x) * 4;
    const float4 v = *(const float4*)(in + i);
    bf16 h[4], l[4];
    split1(v.x, h[0], l[0]); split1(v.y, h[1], l[1]);
    split1(v.z, h[2], l[2]); split1(v.w, h[3], l[3]);
    *(uint2*)(oh + i) = *(const uint2*)h;
    *(uint2*)(ol + i) = *(const uint2*)l;
}

// ---------------------------------------------------------------------------
// Transpose+split: in [R,C] fp32 row-major -> out hi/lo [C,R] bf16. Batched z.
// ---------------------------------------------------------------------------
__global__ __launch_bounds__(256)
void transpose_split(const float* __restrict__ in, bf16* __restrict__ oh,
                     bf16* __restrict__ ol, int R, int C,
                     long long sIn, long long sOut)
{
    __shared__ float t[32][33];
    in += blockIdx.z * sIn;
    oh += blockIdx.z * sOut;
    ol += blockIdx.z * sOut;
    const int x = blockIdx.x * 32 + threadIdx.x;
    const int y = blockIdx.y * 32 + threadIdx.y;
#pragma unroll
    for (int i = 0; i < 4; i++)
        t[threadIdx.y + i * 8][threadIdx.x] = in[(long long)(y + i * 8) * C + x];
    __syncthreads();
    const int xo = blockIdx.y * 32 + threadIdx.x;
    const int yo = blockIdx.x * 32 + threadIdx.y;
#pragma unroll
    for (int i = 0; i < 4; i++) {
        const float val = t[threadIdx.x][threadIdx.y + i * 8];
        bf16 h, l;
        split1(val, h, l);
        const long long o = (long long)(yo + i * 8) * R + xo;
        oh[o] = h;
        ol[o] = l;
    }
}

// ---------------------------------------------------------------------------
// Softmax over rows of 2048: fp32 logits -> hi/lo bf16 probabilities.
// ---------------------------------------------------------------------------
__global__ __launch_bounds__(256)
void softmax_split(const float* __restrict__ logits,
                   bf16* __restrict__ wh, bf16* __restrict__ wl)
{
    const long long row = blockIdx.x;
    const float* p = logits + row * (long long)SEQ;
    const int tid = threadIdx.x;

    __shared__ float red[8];
    __shared__ float bcast;

    float v[8];
    float m = -1e30f;
#pragma unroll
    for (int i = 0; i < 8; i++) {
        v[i] = p[tid + i * 256];
        m = fmaxf(m, v[i]);
    }
#pragma unroll
    for (int o = 16; o > 0; o >>= 1) m = fmaxf(m, __shfl_xor_sync(0xffffffffu, m, o));
    if ((tid & 31) == 0) red[tid >> 5] = m;
    __syncthreads();
    if (tid == 0) {
        float t = red[0];
#pragma unroll
        for (int i = 1; i < 8; i++) t = fmaxf(t, red[i]);
        bcast = t;
    }
    __syncthreads();
    const float rmax = bcast;

    float s = 0.0f;
#pragma unroll
    for (int i = 0; i < 8; i++) {
        v[i] = expf(v[i] - rmax);
        s += v[i];
    }
#pragma unroll
    for (int o = 16; o > 0; o >>= 1) s += __shfl_xor_sync(0xffffffffu, s, o);
    if ((tid & 31) == 0) red[tid >> 5] = s;
    __syncthreads();
    if (tid == 0) {
        float t = 0.0f;
#pragma unroll
        for (int i = 0; i < 8; i++) t += red[i];
        bcast = 1.0f / t;
    }
    __syncthreads();
    const float inv = bcast;

#pragma unroll
    for (int i = 0; i < 8; i++) {
        bf16 h, l;
        split1(v[i] * inv, h, l);
        const long long o = row * (long long)SEQ + tid + i * 256;
        wh[o] = h;
        wl[o] = l;
    }
}

// ---------------------------------------------------------------------------
// GEMM NT on pre-split planes.  C[m,n] = alpha*sum_k(A(m,k)B(n,k)) (+bias[n])
//   CTA 128x256, BK=32, 3 smem stages, 8 warps (2m x 4n), warp tile 64x64.
// SMEM plane layout: [row][k] bf16, row stride 40 bf16 (80B) ->
//   16B-group index (5r + c) mod 8 distinct over 8 rows => conflict-free ldmatrix.
// ---------------------------------------------------------------------------
#define STRIDE_B 80u                 // bytes per smem row
#define A_PLANE  10240u              // 128 * 80
#define B_PLANE  20480u              // 256 * 80
#define OFF_AH   0u
#define OFF_AL   A_PLANE
#define OFF_BH   (2u * A_PLANE)
#define OFF_BL   (2u * A_PLANE + B_PLANE)
#define BUF_B    (2u * A_PLANE + 2u * B_PLANE)   // 61440
#define SMEM_DYN (3u * BUF_B)                    // 184320

template <bool BIAS, bool SPLIT_OUT>
__global__ __launch_bounds__(256)
void gemm_nt(const bf16* __restrict__ ah, const bf16* __restrict__ al,
             const bf16* __restrict__ bh, const bf16* __restrict__ bl,
             const float* __restrict__ bias,
             float* __restrict__ cf, bf16* __restrict__ ch, bf16* __restrict__ cl,
             int N, int K,
             long long sA, long long sB, long long sC, float alpha)
{
    extern __shared__ char dsm[];
    const uint32_t sb = smem_u32(dsm);

    const int tid  = threadIdx.x;
    const int warp = tid >> 5;
    const int lane = tid & 31;
    const int gid  = lane >> 2;
    const int tig  = lane & 3;
    const int wm   = warp & 1;       // 0..1  (m)
    const int wn   = warp >> 1;      // 0..3  (n)

    const long long z = blockIdx.z;
    ah += z * sA;  al += z * sA;
    bh += z * sB;  bl += z * sB;

    const int mbase = blockIdx.y * 128;
    const int nbase = blockIdx.x * 256;

    float acc[4][8][4];
#pragma unroll
    for (int i = 0; i < 4; i++)
#pragma unroll
        for (int j = 0; j < 8; j++)
#pragma unroll
            for (int r = 0; r < 4; r++) acc[i][j][r] = 0.0f;

    // ---- async tile fill: A 1024 chunks (16B), B 2048 chunks ----
    auto load_tile = [&](int t) {
        const uint32_t base = sb + (uint32_t)(t % 3) * BUF_B;
        const int kc = t * 32;
#pragma unroll
        for (int i = 0; i < 4; i++) {                 // A planes
            const int ca = tid + i * 256;             // 0..1023
            const int p  = ca >> 9;                   // 0:hi 1:lo
            const int r  = (ca >> 2) & 127;
            const int c  = ca & 3;
            const bf16* g = (p ? al : ah) + (long long)(mbase + r) * K + kc + c * 8;
            cp16(base + (p ? OFF_AL : OFF_AH) + (uint32_t)r * STRIDE_B + (uint32_t)c * 16u, g);
        }
#pragma unroll
        for (int i = 0; i < 8; i++) {                 // B planes
            const int cb = tid + i * 256;             // 0..2047
            const int p  = cb >> 10;
            const int r  = (cb >> 2) & 255;
            const int c  = cb & 3;
            const bf16* g = (p ? bl : bh) + (long long)(nbase + r) * K + kc + c * 8;
            cp16(base + (p ? OFF_BL : OFF_BH) + (uint32_t)r * STRIDE_B + (uint32_t)c * 16u, g);
        }
        CP_COMMIT();
    };

    const int T = K >> 5;            // K/32
    load_tile(0);
    load_tile(1);

    const int lrow = lane & 15;
    const int lkh  = lane >> 4;      // k-half selector for ldmatrix

    for (int t = 0; t < T; t++) {
        if (t < T - 1) { CP_WAIT1(); } else { CP_WAIT0(); }
        __syncthreads();
        if (t + 2 < T) load_tile(t + 2);

        const uint32_t base = sb + (uint32_t)(t % 3) * BUF_B;
#pragma unroll
        for (int ks = 0; ks < 2; ks++) {
            const uint32_t ko = (uint32_t)ks * 32u + (uint32_t)lkh * 16u;

            uint32_t b_h[8][2], b_l[8][2];
#pragma unroll
            for (int p = 0; p < 4; p++) {            // 16 B-rows per ldmatrix
                const uint32_t ra = (uint32_t)(wn * 64 + p * 16 + lrow) * STRIDE_B + ko;
                ldsm4(b_h[2 * p][0], b_h[2 * p + 1][0],
                      b_h[2 * p][1], b_h[2 * p + 1][1], base + OFF_BH + ra);
                ldsm4(b_l[2 * p][0], b_l[2 * p + 1][0],
                      b_l[2 * p][1], b_l[2 * p + 1][1], base + OFF_BL + ra);
            }
#pragma unroll
            for (int ma = 0; ma < 4; ma++) {
                const uint32_t aa = (uint32_t)(wm * 64 + ma * 16 + lrow) * STRIDE_B + ko;
                uint32_t h0, h1, h2, h3, l0, l1, l2, l3;
                ldsm4(h0, h1, h2, h3, base + OFF_AH + aa);
                ldsm4(l0, l1, l2, l3, base + OFF_AL + aa);
#pragma unroll
                for (int na = 0; na < 8; na++) {
                    mma16816(acc[ma][na], h0, h1, h2, h3, b_h[na][0], b_h[na][1]);
                    mma16816(acc[ma][na], h0, h1, h2, h3, b_l[na][0], b_l[na][1]);
                    mma16816(acc[ma][na], l0, l1, l2, l3, b_h[na][0], b_h[na][1]);
                }
            }
        }
    }

    // ---- epilogue ----
#pragma unroll
    for (int ma = 0; ma < 4; ma++) {
        const int row0 = mbase + wm * 64 + ma * 16 + gid;
#pragma unroll
        for (int na = 0; na < 8; na++) {
            const int col = nbase + wn * 64 + na * 8 + tig * 2;
            float x0 = alpha * acc[ma][na][0], y0 = alpha * acc[ma][na][1];
            float x1 = alpha * acc[ma][na][2], y1 = alpha * acc[ma][na][3];
            if (BIAS) {
                const float b0 = bias[col], b1 = bias[col + 1];
                x0 += b0; y0 += b1; x1 += b0; y1 += b1;
            }
            const long long r0 = (long long)z * sC + (long long)row0 * N + col;
            const long long r1 = r0 + (long long)8 * N;
            if (SPLIT_OUT) {
                bf16 h, l;
                bf16 hp[2], lp[2];
                split1(x0, hp[0], lp[0]); split1(y0, hp[1], lp[1]);
                *(uint32_t*)(ch + r0) = *(const uint32_t*)hp;
                *(uint32_t*)(cl + r0) = *(const uint32_t*)lp;
                split1(x1, hp[0], lp[0]); split1(y1, hp[1], lp[1]);
                *(uint32_t*)(ch + r1) = *(const uint32_t*)hp;
                *(uint32_t*)(cl + r1) = *(const uint32_t*)lp;
                (void)h; (void)l;
            } else {
                *(float2*)(cf + r0) = make_float2(x0, y0);
                *(float2*)(cf + r1) = make_float2(x1, y1);
            }
        }
    }
}

// ---------------------------------------------------------------------------
extern "C" void kernel_launch(void* const* d_in, const int* in_sizes, int n_in,
                              void* d_out, int out_size)
{
    const float* query = (const float*)d_in[0];
    const float* key   = (const float*)d_in[1];
    const float* value = (const float*)d_in[2];
    const float* Wq    = (const float*)d_in[3];
    const float* bq    = (const float*)d_in[4];
    float* out = (float*)d_out;

    bf16 *ih, *il, *wth, *wtl, *qh, *ql, *kh, *kl, *vth, *vtl, *wh, *wl;
    float *vf, *lg;
    cudaGetSymbolAddress((void**)&ih,  g_ih);
    cudaGetSymbolAddress((void**)&il,  g_il);
    cudaGetSymbolAddress((void**)&wth, g_wth);
    cudaGetSymbolAddress((void**)&wtl, g_wtl);
    cudaGetSymbolAddress((void**)&qh,  g_qh);
    cudaGetSymbolAddress((void**)&ql,  g_ql);
    cudaGetSymbolAddress((void**)&kh,  g_kh);
    cudaGetSymbolAddress((void**)&kl,  g_kl);
    cudaGetSymbolAddress((void**)&vf,  g_v);
    cudaGetSymbolAddress((void**)&vth, g_vth);
    cudaGetSymbolAddress((void**)&vtl, g_vtl);
    cudaGetSymbolAddress((void**)&lg,  g_logits);
    cudaGetSymbolAddress((void**)&wh,  g_wh);
    cudaGetSymbolAddress((void**)&wl,  g_wl);

    cudaFuncSetAttribute(gemm_nt<true,  true >, cudaFuncAttributeMaxDynamicSharedMemorySize, SMEM_DYN);
    cudaFuncSetAttribute(gemm_nt<true,  false>, cudaFuncAttributeMaxDynamicSharedMemorySize, SMEM_DYN);
    cudaFuncSetAttribute(gemm_nt<false, false>, cudaFuncAttributeMaxDynamicSharedMemorySize, SMEM_DYN);

    const long long nElem = (long long)NROWS * DIM;
    const dim3 tb(256);

    // W^T hi/lo planes
    transpose_split<<<dim3(DIM / 32, DIM / 32, 1), dim3(32, 8)>>>(Wq, wth, wtl, DIM, DIM, 0, 0);

    // ---- stage 1: projections (M=16384, N=1024, K=1024) ----
    {
        const dim3 g(DIM / 256, NROWS / 128, 1);
        split_pass<<<nElem / 1024, tb>>>(query, ih, il);
        gemm_nt<true, true><<<g, tb, SMEM_DYN>>>(ih, il, wth, wtl, bq,
                                                 nullptr, qh, ql, DIM, DIM, 0, 0, 0, 1.0f);
        split_pass<<<nElem / 1024, tb>>>(key, ih, il);
        gemm_nt<true, true><<<g, tb, SMEM_DYN>>>(ih, il, wth, wtl, bq,
                                                 nullptr, kh, kl, DIM, DIM, 0, 0, 0, 1.0f);
        split_pass<<<nElem / 1024, tb>>>(value, ih, il);
        gemm_nt<true, false><<<g, tb, SMEM_DYN>>>(ih, il, wth, wtl, bq,
                                                  vf, nullptr, nullptr, DIM, DIM, 0, 0, 0, 1.0f);
    }

    // v^T hi/lo per batch: [S,D] -> [D,S]
    transpose_split<<<dim3(DIM / 32, SEQ / 32, BATCH), dim3(32, 8)>>>(
        vf, vth, vtl, SEQ, DIM, (long long)SEQ * DIM, (long long)SEQ * DIM);

    // ---- stage 2: logits = q k^T / 32  (M=N=2048, K=1024, batched) ----
    {
        const dim3 g(SEQ / 256, SEQ / 128, BATCH);
        gemm_nt<false, false><<<g, tb, SMEM_DYN>>>(qh, ql, kh, kl, nullptr,
                                                   lg, nullptr, nullptr, SEQ, DIM,
                                                   (long long)SEQ * DIM, (long long)SEQ * DIM,
                                                   (long long)SEQ * SEQ, 0.03125f);
    }

    // ---- stage 3: softmax + split ----
    softmax_split<<<NROWS, tb>>>(lg, wh, wl);

    // ---- stage 4: out = w v^T_planes  (M=2048, N=1024, K=2048, batched) ----
    {
        const dim3 g(DIM / 256, SEQ / 128, BATCH);
        gemm_nt<false, false><<<g, tb, SMEM_DYN>>>(wh, wl, vth, vtl, nullptr,
                                                   out, nullptr, nullptr, DIM, SEQ,
                                                   (long long)SEQ * SEQ, (long long)SEQ * DIM,
                                                   (long long)SEQ * DIM, 1.0f);
    }
}